// round 2
// baseline (speedup 1.0000x reference)
#include <cuda_runtime.h>
#include <math.h>

// Problem constants
#define BB 64      // batch
#define TT 256     // time steps
#define DD 1024    // input dim
#define HH 1024    // hidden dim
#define LL 4       // layers
#define GG 4096    // 4*H gate width
#define NBLK 128   // persistent grid size (<= 148 SMs -> co-resident)

typedef unsigned long long ull;

// ---------------------------------------------------------------------------
// Scratch (static device globals; no runtime allocation allowed)
// ---------------------------------------------------------------------------
__device__ float g_gx[(size_t)TT * BB * GG];    // [T*B, 4H] input-side gate pre-activations
__device__ float g_hseq[(size_t)TT * BB * HH];  // [T, B, H] layer output sequence
__device__ float g_hbuf[2][BB][HH];             // double-buffered hidden state
__device__ unsigned g_bar_count;                // grid barrier state (zero-init)
__device__ volatile unsigned g_bar_gen;

// ---------------------------------------------------------------------------
// Packed fp32x2 helpers (sm_103a FFMA2 path — 2x fp32 FMA rate)
// ---------------------------------------------------------------------------
__device__ __forceinline__ ull pack2(float v) {
    ull r; asm("mov.b64 %0,{%1,%1};" : "=l"(r) : "f"(v)); return r;
}
__device__ __forceinline__ void ffma2(ull& d, ull a, ull b) {
    asm("fma.rn.f32x2 %0,%1,%2,%0;" : "+l"(d) : "l"(a), "l"(b));
}
__device__ __forceinline__ float2 unpack2(ull v) {
    float2 f; asm("mov.b64 {%0,%1},%2;" : "=f"(f.x), "=f"(f.y) : "l"(v)); return f;
}

// ---------------------------------------------------------------------------
// Software grid barrier (all NBLK blocks co-resident; fence-cumulative pattern)
// ---------------------------------------------------------------------------
__device__ __forceinline__ void grid_sync() {
    __syncthreads();
    if (threadIdx.x == 0) {
        __threadfence();
        unsigned gen = g_bar_gen;
        if (atomicAdd(&g_bar_count, 1u) == NBLK - 1) {
            g_bar_count = 0;
            __threadfence();
            g_bar_gen = gen + 1;
        } else {
            while (g_bar_gen == gen) { }
            __threadfence();
        }
    }
    __syncthreads();
}

// ---------------------------------------------------------------------------
// Big input GEMM: g_gx[m][n] = sum_k A[m][k] * W[k][n] + bias[n]
//   m = t*B + b ; Layer 0: A = x [B,T,D]; Layer>0: A = g_hseq [T,B,H]
// 128x128 tile, BK=8, 256 threads, 8x8 micro-tile, f32x2 inner product.
// ---------------------------------------------------------------------------
__global__ __launch_bounds__(256) void gemm_in_kernel(
    const float* __restrict__ xin, long sT, long sB,
    const float* __restrict__ W, const float* __restrict__ bias,
    int use_hseq)
{
    __shared__ float As[8][128];   // As[k][row]
    __shared__ float Ws[8][128];   // Ws[k][col]

    const float* A = use_hseq ? (const float*)g_hseq : xin;

    int tid = threadIdx.x;

    // A loader: 128 rows x 8 k
    int aRow = tid >> 1;
    int aK   = (tid & 1) * 4;
    int m    = blockIdx.y * 128 + aRow;
    const float* Arow = A + (size_t)(m & (BB - 1)) * sB + (size_t)(m >> 6) * sT;

    // W loader: 8 k x 128 cols
    int wK   = tid >> 5;
    int wCol = (tid & 31) * 4;
    const float* Wp = W + (size_t)wK * GG + blockIdx.x * 128 + wCol;

    int trow = tid >> 4;
    int tcol = tid & 15;

    ull acc[8][4];
#pragma unroll
    for (int i = 0; i < 8; i++)
#pragma unroll
        for (int j = 0; j < 4; j++) acc[i][j] = 0ull;

    for (int k0 = 0; k0 < 1024; k0 += 8) {
        float4 av = *(const float4*)(Arow + k0 + aK);
        As[aK + 0][aRow] = av.x;
        As[aK + 1][aRow] = av.y;
        As[aK + 2][aRow] = av.z;
        As[aK + 3][aRow] = av.w;
        *(float4*)&Ws[wK][wCol] = *(const float4*)(Wp + (size_t)k0 * GG);
        __syncthreads();

#pragma unroll
        for (int k = 0; k < 8; ++k) {
            float4 a0 = *(const float4*)&As[k][trow * 8];
            float4 a1 = *(const float4*)&As[k][trow * 8 + 4];
            ull pa[8];
            pa[0] = pack2(a0.x); pa[1] = pack2(a0.y);
            pa[2] = pack2(a0.z); pa[3] = pack2(a0.w);
            pa[4] = pack2(a1.x); pa[5] = pack2(a1.y);
            pa[6] = pack2(a1.z); pa[7] = pack2(a1.w);
            ulonglong2 w01 = *(const ulonglong2*)&Ws[k][tcol * 8];
            ulonglong2 w23 = *(const ulonglong2*)&Ws[k][tcol * 8 + 4];
#pragma unroll
            for (int i = 0; i < 8; i++) {
                ffma2(acc[i][0], pa[i], w01.x);
                ffma2(acc[i][1], pa[i], w01.y);
                ffma2(acc[i][2], pa[i], w23.x);
                ffma2(acc[i][3], pa[i], w23.y);
            }
        }
        __syncthreads();
    }

    int rowBase = blockIdx.y * 128 + trow * 8;
    int colBase = blockIdx.x * 128 + tcol * 8;
    float4 b0 = *(const float4*)&bias[colBase];
    float4 b1 = *(const float4*)&bias[colBase + 4];
    float bb[8] = {b0.x, b0.y, b0.z, b0.w, b1.x, b1.y, b1.z, b1.w};

#pragma unroll
    for (int i = 0; i < 8; i++) {
        size_t off = (size_t)(rowBase + i) * GG + colBase;
        float2 v0 = unpack2(acc[i][0]);
        float2 v1 = unpack2(acc[i][1]);
        float2 v2 = unpack2(acc[i][2]);
        float2 v3 = unpack2(acc[i][3]);
        float4 o0 = make_float4(v0.x + bb[0], v0.y + bb[1], v1.x + bb[2], v1.y + bb[3]);
        float4 o1 = make_float4(v2.x + bb[4], v2.y + bb[5], v3.x + bb[6], v3.y + bb[7]);
        *(float4*)&g_gx[off]     = o0;
        *(float4*)&g_gx[off + 4] = o1;
    }
}

// ---------------------------------------------------------------------------
// Persistent recurrence kernel (one launch per layer, all 256 timesteps).
// Block b owns hidden cols [b*8, b*8+8) -> gate cols {c, 1024+c, 2048+c, 3072+c}.
// Per step: 64x32x1024 GEMM tile (h @ Wh), add gx, LSTM cell locally,
// write h to double buffer + output; ONE grid barrier per step.
// ---------------------------------------------------------------------------
__global__ __launch_bounds__(256) void layer_recur_kernel(
    const float* __restrict__ Wh,   // [1024][4096] this layer
    float* __restrict__ outp, int is_last)
{
    __shared__ float As[32][68];    // h chunk, transposed, padded
    __shared__ float Ws[32][32];    // Wh chunk
    __shared__ float gsm[64][36];   // gates (padded for 16B-aligned rows)
    __shared__ float csm[64][8];    // persistent cell state for this block

    const int tid = threadIdx.x;
    const int b   = blockIdx.x;
    const int j0  = b * 8;

    float* dst = is_last ? outp : (float*)g_hseq;

    // init: zero own columns of h buffer 0 and cell state
    {
        int r = tid >> 2;
        int c = (tid & 3) * 2;
        g_hbuf[0][r][j0 + c]     = 0.0f;
        g_hbuf[0][r][j0 + c + 1] = 0.0f;
        csm[r][c]     = 0.0f;
        csm[r][c + 1] = 0.0f;
    }
    grid_sync();

    // GEMM micro-tile: 2 rows x 4 cols per thread (32 x 8 thread grid)
    const int r0 = 2 * (tid >> 3);
    const int c0 = (tid & 7) * 4;
    const int chunk = c0 >> 3;
    const int gcol  = chunk * 1024 + j0 + (c0 & 7);   // global gate col (float4 base)

    // staging indices
    const int hrow = tid >> 2;            // 0..63 (coalesced h loads)
    const int hk0  = (tid & 3) * 4;       // 0,4,8,12 (+16 for second half)
    const int wkk  = tid >> 3;            // 0..31
    const int wc   = (tid & 7) * 4;       // local col (float4)
    const int wchunk = wc >> 3;
    const int wgcol  = wchunk * 1024 + j0 + (wc & 7);

    // cell-update indices: 2 elements per thread over 64x8
    const int er = tid >> 2;
    const int ec = (tid & 3) * 2;

    for (int t = 0; t < TT; ++t) {
        ull acc00 = 0ull, acc01 = 0ull, acc10 = 0ull, acc11 = 0ull;

        if (t > 0) {
            const float* h = &g_hbuf[t & 1][0][0];
            for (int k0 = 0; k0 < HH; k0 += 32) {
                // stage h chunk [64 rows x 32 k] transposed
                float4 h0 = *(const float4*)(h + (size_t)hrow * HH + k0 + hk0);
                float4 h1 = *(const float4*)(h + (size_t)hrow * HH + k0 + 16 + hk0);
                As[hk0 + 0][hrow] = h0.x;  As[hk0 + 1][hrow] = h0.y;
                As[hk0 + 2][hrow] = h0.z;  As[hk0 + 3][hrow] = h0.w;
                As[hk0 + 16][hrow] = h1.x; As[hk0 + 17][hrow] = h1.y;
                As[hk0 + 18][hrow] = h1.z; As[hk0 + 19][hrow] = h1.w;
                // stage Wh chunk [32 k x 32 cols]
                *(float4*)&Ws[wkk][wc] =
                    *(const float4*)(Wh + (size_t)(k0 + wkk) * GG + wgcol);
                __syncthreads();

#pragma unroll
                for (int k = 0; k < 32; ++k) {
                    float2 a2 = *(const float2*)&As[k][r0];
                    ull pa0 = pack2(a2.x);
                    ull pa1 = pack2(a2.y);
                    ulonglong2 w2 = *(const ulonglong2*)&Ws[k][c0];
                    ffma2(acc00, pa0, w2.x); ffma2(acc01, pa0, w2.y);
                    ffma2(acc10, pa1, w2.x); ffma2(acc11, pa1, w2.y);
                }
                __syncthreads();
            }
        }

        // add input-side gates and stash in smem
        {
            size_t gb0 = ((size_t)t * BB + r0) * GG + gcol;
            float4 gx0 = *(const float4*)&g_gx[gb0];
            float4 gx1 = *(const float4*)&g_gx[gb0 + GG];
            float2 v;
            v = unpack2(acc00); gsm[r0][c0 + 0] = gx0.x + v.x; gsm[r0][c0 + 1] = gx0.y + v.y;
            v = unpack2(acc01); gsm[r0][c0 + 2] = gx0.z + v.x; gsm[r0][c0 + 3] = gx0.w + v.y;
            v = unpack2(acc10); gsm[r0 + 1][c0 + 0] = gx1.x + v.x; gsm[r0 + 1][c0 + 1] = gx1.y + v.y;
            v = unpack2(acc11); gsm[r0 + 1][c0 + 2] = gx1.z + v.x; gsm[r0 + 1][c0 + 3] = gx1.w + v.y;
        }
        __syncthreads();

        // LSTM cell: block-local (all 4 gate chunks for our h-cols are in gsm)
#pragma unroll
        for (int i = 0; i < 2; ++i) {
            int cc = ec + i;
            float zi = gsm[er][cc];
            float zf = gsm[er][8 + cc];
            float zg = gsm[er][16 + cc];
            float zo = gsm[er][24 + cc];
            float ig = 1.0f / (1.0f + expf(-zi));
            float fg = 1.0f / (1.0f + expf(-zf));
            float og = 1.0f / (1.0f + expf(-zo));
            float gg = tanhf(zg);
            float cv = fg * csm[er][cc] + ig * gg;
            float hv = og * tanhf(cv);
            csm[er][cc] = cv;
            g_hbuf[(t + 1) & 1][er][j0 + cc] = hv;
            dst[(size_t)t * (BB * HH) + (size_t)er * HH + j0 + cc] = hv;
        }

        grid_sync();   // h(t) fully published before step t+1 reads it
    }
}

// ---------------------------------------------------------------------------
// Host launcher: 8 graph nodes total (4 big GEMMs + 4 persistent layers)
// Inputs: x [B,T,D], Wx [L,D,4H], Wh [L,H,4H], b [L,4H]. Output [T,B,H].
// ---------------------------------------------------------------------------
extern "C" void kernel_launch(void* const* d_in, const int* in_sizes, int n_in,
                              void* d_out, int out_size)
{
    const float* x    = (const float*)d_in[0];
    const float* Wx   = (const float*)d_in[1];
    const float* Wh   = (const float*)d_in[2];
    const float* bias = (const float*)d_in[3];
    float* out = (float*)d_out;

    dim3 gemm_grid(GG / 128, (TT * BB) / 128);   // (32, 128)

    for (int l = 0; l < LL; ++l) {
        long sT = (l == 0) ? (long)DD : (long)BB * HH;
        long sB = (l == 0) ? (long)TT * DD : (long)HH;

        gemm_in_kernel<<<gemm_grid, 256>>>(
            x, sT, sB,
            Wx + (size_t)l * DD * GG,
            bias + (size_t)l * GG,
            (l == 0) ? 0 : 1);

        layer_recur_kernel<<<NBLK, 256>>>(
            Wh + (size_t)l * HH * GG,
            out,
            (l == LL - 1) ? 1 : 0);
    }
}